// round 12
// baseline (speedup 1.0000x reference)
#include <cuda_runtime.h>
#include <math.h>
#include <stdint.h>

// NGP multiresolution hash-grid interpolation encoding, with Morton bucket
// sort so warp lanes are spatially adjacent -> gather cache-line sharing.
// Round 7 (resubmit after infra failure): permute fused into main kernel
// (smem transpose store), finer Morton buckets (32768), 2x level unroll.
// B=262144 points, DIM=3, L=16 levels, T=19, F=2.

#define NGP_L 16
#define NGP_T 19
#define NGP_MASK ((1u << NGP_T) - 1u)
#define NGP_P1 2654435761u
#define NGP_P2 805459861u
#define BMAX 262144
#define NB 32768           // 32^3 Morton buckets (5 bits/axis)

struct ResParams { float r[NGP_L]; };

__device__ unsigned g_hist[NB];
__device__ unsigned g_off[NB];
__device__ float4   g_pk[BMAX];   // sorted (x, y, z, orig_idx_bits)

__device__ __forceinline__ unsigned spread5(unsigned v) {
    // 5-bit v -> bits at positions 0,3,6,9,12
    return (v & 1u) | ((v & 2u) << 2) | ((v & 4u) << 4) | ((v & 8u) << 6) | ((v & 16u) << 8);
}

__device__ __forceinline__ unsigned bucket_of(float x0, float x1, float x2) {
    unsigned bx = (unsigned)(x0 * 32.0f); if (bx > 31u) bx = 31u;
    unsigned by = (unsigned)(x1 * 32.0f); if (by > 31u) by = 31u;
    unsigned bz = (unsigned)(x2 * 32.0f); if (bz > 31u) bz = 31u;
    return spread5(bx) | (spread5(by) << 1) | (spread5(bz) << 2);
}

__global__ void k_hist(const float* __restrict__ x, int n) {
    int b = blockIdx.x * 256 + threadIdx.x;
    if (b >= n) return;
    atomicAdd(&g_hist[bucket_of(x[3*b], x[3*b+1], x[3*b+2])], 1u);
}

// exclusive scan of g_hist (32768 = 1024 threads x 32) -> g_off
__global__ void __launch_bounds__(1024) k_scan() {
    __shared__ unsigned s[1024];
    int t = threadIdx.x;
    unsigned loc[32];
    unsigned sum = 0;
    #pragma unroll
    for (int i = 0; i < 32; i++) { loc[i] = g_hist[t * 32 + i]; sum += loc[i]; }
    s[t] = sum;
    __syncthreads();
    for (int d = 1; d < 1024; d <<= 1) {
        unsigned v = (t >= d) ? s[t-d] : 0u;
        __syncthreads();
        s[t] += v;
        __syncthreads();
    }
    unsigned excl = (t == 0) ? 0u : s[t-1];
    #pragma unroll
    for (int i = 0; i < 32; i++) { g_off[t * 32 + i] = excl; excl += loc[i]; }
}

__global__ void k_scatter(const float* __restrict__ x, int n) {
    int b = blockIdx.x * 256 + threadIdx.x;
    if (b >= n) return;
    float x0 = x[3*b], x1 = x[3*b+1], x2 = x[3*b+2];
    unsigned p = atomicAdd(&g_off[bucket_of(x0, x1, x2)], 1u);
    g_pk[p] = make_float4(x0, x1, x2, __uint_as_float((unsigned)b));
}

// Main: thread = one sorted point, loops all 16 levels; results staged in
// smem, then per-warp transpose store: each STG's 32 lanes cover exactly one
// point's 128B output row (1 store line per point).
__global__ void __launch_bounds__(256) k_main(
    const float2* __restrict__ tables, ResParams rp, int n,
    float* __restrict__ outf)
{
    __shared__ float    sv[8][32][33];
    __shared__ unsigned so[8][32];
    int w = threadIdx.x >> 5, lane = threadIdx.x & 31;
    int pos = blockIdx.x * 256 + threadIdx.x;
    bool act = pos < n;

    if (act) {
        float4 pk = g_pk[pos];
        float x0 = pk.x, x1 = pk.y, x2 = pk.z;
        so[w][lane] = __float_as_uint(pk.w);

        #pragma unroll 2
        for (int l = 0; l < NGP_L; l++) {
            float res = rp.r[l];
            float sx = x0 * res, sy = x1 * res, sz = x2 * res;
            float fx = floorf(sx), fy = floorf(sy), fz = floorf(sz);
            unsigned gx = (unsigned)fx, gy = (unsigned)fy, gz = (unsigned)fz;
            float tx = sx - fx, ty = sy - fy, tz = sz - fz;

            unsigned hx0 = gx,          hx1 = gx + 1u;
            unsigned hy0 = gy * NGP_P1, hy1 = hy0 + NGP_P1;
            unsigned hz0 = gz * NGP_P2, hz1 = hz0 + NGP_P2;

            const float2* __restrict__ tbl = tables + ((size_t)l << NGP_T);

            unsigned i0 = (hx0 ^ hy0 ^ hz0) & NGP_MASK;
            unsigned i1 = (hx1 ^ hy0 ^ hz0) & NGP_MASK;
            unsigned i2 = (hx0 ^ hy1 ^ hz0) & NGP_MASK;
            unsigned i3 = (hx1 ^ hy1 ^ hz0) & NGP_MASK;
            unsigned i4 = (hx0 ^ hy0 ^ hz1) & NGP_MASK;
            unsigned i5 = (hx1 ^ hy0 ^ hz1) & NGP_MASK;
            unsigned i6 = (hx0 ^ hy1 ^ hz1) & NGP_MASK;
            unsigned i7 = (hx1 ^ hy1 ^ hz1) & NGP_MASK;

            float2 v0 = __ldg(tbl + i0);
            float2 v1 = __ldg(tbl + i1);
            float2 v2 = __ldg(tbl + i2);
            float2 v3 = __ldg(tbl + i3);
            float2 v4 = __ldg(tbl + i4);
            float2 v5 = __ldg(tbl + i5);
            float2 v6 = __ldg(tbl + i6);
            float2 v7 = __ldg(tbl + i7);

            float wx0 = 1.0f - tx, wy0 = 1.0f - ty, wz0 = 1.0f - tz;
            float w00 = wx0 * wy0, w10 = tx * wy0, w01 = wx0 * ty, w11 = tx * ty;

            float a0 = 0.0f, a1 = 0.0f, wt;
            wt = w00 * wz0; a0 = fmaf(wt, v0.x, a0); a1 = fmaf(wt, v0.y, a1);
            wt = w10 * wz0; a0 = fmaf(wt, v1.x, a0); a1 = fmaf(wt, v1.y, a1);
            wt = w01 * wz0; a0 = fmaf(wt, v2.x, a0); a1 = fmaf(wt, v2.y, a1);
            wt = w11 * wz0; a0 = fmaf(wt, v3.x, a0); a1 = fmaf(wt, v3.y, a1);
            wt = w00 * tz;  a0 = fmaf(wt, v4.x, a0); a1 = fmaf(wt, v4.y, a1);
            wt = w10 * tz;  a0 = fmaf(wt, v5.x, a0); a1 = fmaf(wt, v5.y, a1);
            wt = w01 * tz;  a0 = fmaf(wt, v6.x, a0); a1 = fmaf(wt, v6.y, a1);
            wt = w11 * tz;  a0 = fmaf(wt, v7.x, a0); a1 = fmaf(wt, v7.y, a1);

            sv[w][lane][2*l]   = a0;
            sv[w][lane][2*l+1] = a1;
        }
    }
    __syncwarp();

    int base = blockIdx.x * 256 + w * 32;
    int cnt = n - base; if (cnt > 32) cnt = 32; if (cnt < 0) cnt = 0;
    for (int p = 0; p < cnt; p++) {
        float val  = sv[w][p][lane];
        unsigned o = so[w][p];
        outf[(size_t)o * 32 + lane] = val;
    }
}

// Fallback (round-1 style flat kernel) if npts exceeds scratch capacity.
__global__ void __launch_bounds__(256, 8) ngp_flat_kernel(
    const float* __restrict__ x, const float2* __restrict__ tables,
    float2* __restrict__ out, ResParams rp, int npts)
{
    int t = blockIdx.x * 256 + threadIdx.x;
    int b = t >> 4, l = t & 15;
    if (b >= npts) return;
    float res = rp.r[l];
    float sx = __ldg(x+3*b) * res, sy = __ldg(x+3*b+1) * res, sz = __ldg(x+3*b+2) * res;
    float fx = floorf(sx), fy = floorf(sy), fz = floorf(sz);
    unsigned gx = (unsigned)fx, gy = (unsigned)fy, gz = (unsigned)fz;
    float tx = sx-fx, ty = sy-fy, tz = sz-fz;
    unsigned hx0 = gx, hx1 = gx+1u;
    unsigned hy0 = gy*NGP_P1, hy1 = hy0+NGP_P1;
    unsigned hz0 = gz*NGP_P2, hz1 = hz0+NGP_P2;
    const float2* __restrict__ tbl = tables + ((size_t)l << NGP_T);
    float2 v0 = __ldg(tbl + ((hx0^hy0^hz0)&NGP_MASK));
    float2 v1 = __ldg(tbl + ((hx1^hy0^hz0)&NGP_MASK));
    float2 v2 = __ldg(tbl + ((hx0^hy1^hz0)&NGP_MASK));
    float2 v3 = __ldg(tbl + ((hx1^hy1^hz0)&NGP_MASK));
    float2 v4 = __ldg(tbl + ((hx0^hy0^hz1)&NGP_MASK));
    float2 v5 = __ldg(tbl + ((hx1^hy0^hz1)&NGP_MASK));
    float2 v6 = __ldg(tbl + ((hx0^hy1^hz1)&NGP_MASK));
    float2 v7 = __ldg(tbl + ((hx1^hy1^hz1)&NGP_MASK));
    float wx0 = 1.0f-tx, wy0 = 1.0f-ty, wz0 = 1.0f-tz;
    float w00 = wx0*wy0, w10 = tx*wy0, w01 = wx0*ty, w11 = tx*ty;
    float a0 = 0.f, a1 = 0.f, w;
    w = w00*wz0; a0 = fmaf(w,v0.x,a0); a1 = fmaf(w,v0.y,a1);
    w = w10*wz0; a0 = fmaf(w,v1.x,a0); a1 = fmaf(w,v1.y,a1);
    w = w01*wz0; a0 = fmaf(w,v2.x,a0); a1 = fmaf(w,v2.y,a1);
    w = w11*wz0; a0 = fmaf(w,v3.x,a0); a1 = fmaf(w,v3.y,a1);
    w = w00*tz;  a0 = fmaf(w,v4.x,a0); a1 = fmaf(w,v4.y,a1);
    w = w10*tz;  a0 = fmaf(w,v5.x,a0); a1 = fmaf(w,v5.y,a1);
    w = w01*tz;  a0 = fmaf(w,v6.x,a0); a1 = fmaf(w,v6.y,a1);
    w = w11*tz;  a0 = fmaf(w,v7.x,a0); a1 = fmaf(w,v7.y,a1);
    out[(size_t)b*16 + l] = make_float2(a0, a1);
}

extern "C" void kernel_launch(void* const* d_in, const int* in_sizes, int n_in,
                              void* d_out, int out_size)
{
    const float* x = (const float*)d_in[0];
    const float2* tables = (const float2*)d_in[1];
    int npts = in_sizes[0] / 3;

    // Replicate numpy's RES computation bit-for-bit in float64 (same libm,
    // incl. numpy's pow shortcuts). RES is exactly integral at levels
    // 0,3,6,9,12,15, so independent recomputation risks off-by-one in floor.
    ResParams rp;
    double bb = exp((log(512.0) - log(16.0)) / 15.0);
    for (int l = 0; l < NGP_L; l++) {
        double p;
        if (l == 0)      p = 1.0;
        else if (l == 1) p = bb;
        else if (l == 2) p = bb * bb;
        else             p = pow(bb, (double)l);
        rp.r[l] = (float)floor(16.0 * p);
    }

    if (npts > BMAX) {
        int total = npts * 16;
        ngp_flat_kernel<<<(total + 255) / 256, 256>>>(x, tables, (float2*)d_out, rp, npts);
        return;
    }

    void* histAddr = nullptr;
    cudaGetSymbolAddress(&histAddr, g_hist);
    cudaMemsetAsync(histAddr, 0, NB * sizeof(unsigned));

    int blocks = (npts + 255) / 256;
    k_hist<<<blocks, 256>>>(x, npts);
    k_scan<<<1, 1024>>>();
    k_scatter<<<blocks, 256>>>(x, npts);
    k_main<<<blocks, 256>>>(tables, rp, npts, (float*)d_out);
}

// round 16
// speedup vs baseline: 1.0437x; 1.0437x over previous
#include <cuda_runtime.h>
#include <math.h>
#include <stdint.h>

// NGP multiresolution hash-grid interpolation encoding, with Morton bucket
// sort so warp lanes are spatially adjacent -> gather cache-line sharing.
// Round 13: fused transpose store kept, but the level loop reverted to the
// round-6 shape (#pragma unroll 1, 8 batched gathers, ~30 regs) and 128-thread
// CTAs so smem staging doesn't choke occupancy or gather MLP.
// B=262144 points, DIM=3, L=16 levels, T=19, F=2.

#define NGP_L 16
#define NGP_T 19
#define NGP_MASK ((1u << NGP_T) - 1u)
#define NGP_P1 2654435761u
#define NGP_P2 805459861u
#define BMAX 262144
#define NB 32768           // 32^3 Morton buckets (5 bits/axis)

struct ResParams { float r[NGP_L]; };

__device__ unsigned g_hist[NB];
__device__ unsigned g_off[NB];
__device__ float4   g_pk[BMAX];   // sorted (x, y, z, orig_idx_bits)

__device__ __forceinline__ unsigned spread5(unsigned v) {
    return (v & 1u) | ((v & 2u) << 2) | ((v & 4u) << 4) | ((v & 8u) << 6) | ((v & 16u) << 8);
}

__device__ __forceinline__ unsigned bucket_of(float x0, float x1, float x2) {
    unsigned bx = (unsigned)(x0 * 32.0f); if (bx > 31u) bx = 31u;
    unsigned by = (unsigned)(x1 * 32.0f); if (by > 31u) by = 31u;
    unsigned bz = (unsigned)(x2 * 32.0f); if (bz > 31u) bz = 31u;
    return spread5(bx) | (spread5(by) << 1) | (spread5(bz) << 2);
}

__global__ void k_hist(const float* __restrict__ x, int n) {
    int b = blockIdx.x * 256 + threadIdx.x;
    if (b >= n) return;
    atomicAdd(&g_hist[bucket_of(x[3*b], x[3*b+1], x[3*b+2])], 1u);
}

// exclusive scan of g_hist (32768 = 1024 threads x 32) -> g_off
__global__ void __launch_bounds__(1024) k_scan() {
    __shared__ unsigned s[1024];
    int t = threadIdx.x;
    unsigned loc[32];
    unsigned sum = 0;
    #pragma unroll
    for (int i = 0; i < 32; i++) { loc[i] = g_hist[t * 32 + i]; sum += loc[i]; }
    s[t] = sum;
    __syncthreads();
    for (int d = 1; d < 1024; d <<= 1) {
        unsigned v = (t >= d) ? s[t-d] : 0u;
        __syncthreads();
        s[t] += v;
        __syncthreads();
    }
    unsigned excl = (t == 0) ? 0u : s[t-1];
    #pragma unroll
    for (int i = 0; i < 32; i++) { g_off[t * 32 + i] = excl; excl += loc[i]; }
}

__global__ void k_scatter(const float* __restrict__ x, int n) {
    int b = blockIdx.x * 256 + threadIdx.x;
    if (b >= n) return;
    float x0 = x[3*b], x1 = x[3*b+1], x2 = x[3*b+2];
    unsigned p = atomicAdd(&g_off[bucket_of(x0, x1, x2)], 1u);
    g_pk[p] = make_float4(x0, x1, x2, __uint_as_float((unsigned)b));
}

// Main: thread = one sorted point, loops all 16 levels (one level in flight,
// 8 batched gathers). Results staged in smem; per-warp transpose store so
// each STG's 32 lanes cover exactly one point's 128B output row.
__global__ void __launch_bounds__(128) k_main(
    const float2* __restrict__ tables, ResParams rp, int n,
    float* __restrict__ outf)
{
    __shared__ float    sv[4][32][33];
    __shared__ unsigned so[4][32];
    int w = threadIdx.x >> 5, lane = threadIdx.x & 31;
    int pos = blockIdx.x * 128 + threadIdx.x;

    if (pos < n) {
        float4 pk = g_pk[pos];
        float x0 = pk.x, x1 = pk.y, x2 = pk.z;
        so[w][lane] = __float_as_uint(pk.w);

        #pragma unroll 1
        for (int l = 0; l < NGP_L; l++) {
            float res = rp.r[l];
            float sx = x0 * res, sy = x1 * res, sz = x2 * res;
            float fx = floorf(sx), fy = floorf(sy), fz = floorf(sz);
            unsigned gx = (unsigned)fx, gy = (unsigned)fy, gz = (unsigned)fz;
            float tx = sx - fx, ty = sy - fy, tz = sz - fz;

            unsigned hx0 = gx,          hx1 = gx + 1u;
            unsigned hy0 = gy * NGP_P1, hy1 = hy0 + NGP_P1;
            unsigned hz0 = gz * NGP_P2, hz1 = hz0 + NGP_P2;

            const float2* __restrict__ tbl = tables + ((size_t)l << NGP_T);

            unsigned i0 = (hx0 ^ hy0 ^ hz0) & NGP_MASK;
            unsigned i1 = (hx1 ^ hy0 ^ hz0) & NGP_MASK;
            unsigned i2 = (hx0 ^ hy1 ^ hz0) & NGP_MASK;
            unsigned i3 = (hx1 ^ hy1 ^ hz0) & NGP_MASK;
            unsigned i4 = (hx0 ^ hy0 ^ hz1) & NGP_MASK;
            unsigned i5 = (hx1 ^ hy0 ^ hz1) & NGP_MASK;
            unsigned i6 = (hx0 ^ hy1 ^ hz1) & NGP_MASK;
            unsigned i7 = (hx1 ^ hy1 ^ hz1) & NGP_MASK;

            float2 v0 = __ldg(tbl + i0);
            float2 v1 = __ldg(tbl + i1);
            float2 v2 = __ldg(tbl + i2);
            float2 v3 = __ldg(tbl + i3);
            float2 v4 = __ldg(tbl + i4);
            float2 v5 = __ldg(tbl + i5);
            float2 v6 = __ldg(tbl + i6);
            float2 v7 = __ldg(tbl + i7);

            float wx0 = 1.0f - tx, wy0 = 1.0f - ty, wz0 = 1.0f - tz;
            float w00 = wx0 * wy0, w10 = tx * wy0, w01 = wx0 * ty, w11 = tx * ty;

            float a0 = 0.0f, a1 = 0.0f, wt;
            wt = w00 * wz0; a0 = fmaf(wt, v0.x, a0); a1 = fmaf(wt, v0.y, a1);
            wt = w10 * wz0; a0 = fmaf(wt, v1.x, a0); a1 = fmaf(wt, v1.y, a1);
            wt = w01 * wz0; a0 = fmaf(wt, v2.x, a0); a1 = fmaf(wt, v2.y, a1);
            wt = w11 * wz0; a0 = fmaf(wt, v3.x, a0); a1 = fmaf(wt, v3.y, a1);
            wt = w00 * tz;  a0 = fmaf(wt, v4.x, a0); a1 = fmaf(wt, v4.y, a1);
            wt = w10 * tz;  a0 = fmaf(wt, v5.x, a0); a1 = fmaf(wt, v5.y, a1);
            wt = w01 * tz;  a0 = fmaf(wt, v6.x, a0); a1 = fmaf(wt, v6.y, a1);
            wt = w11 * tz;  a0 = fmaf(wt, v7.x, a0); a1 = fmaf(wt, v7.y, a1);

            sv[w][lane][2*l]   = a0;
            sv[w][lane][2*l+1] = a1;
        }
    }
    __syncwarp();

    int base = blockIdx.x * 128 + w * 32;
    int cnt = n - base; if (cnt > 32) cnt = 32; if (cnt < 0) cnt = 0;
    for (int p = 0; p < cnt; p++) {
        float val  = sv[w][p][lane];
        unsigned o = so[w][p];
        outf[(size_t)o * 32 + lane] = val;
    }
}

// Fallback (round-1 style flat kernel) if npts exceeds scratch capacity.
__global__ void __launch_bounds__(256, 8) ngp_flat_kernel(
    const float* __restrict__ x, const float2* __restrict__ tables,
    float2* __restrict__ out, ResParams rp, int npts)
{
    int t = blockIdx.x * 256 + threadIdx.x;
    int b = t >> 4, l = t & 15;
    if (b >= npts) return;
    float res = rp.r[l];
    float sx = __ldg(x+3*b) * res, sy = __ldg(x+3*b+1) * res, sz = __ldg(x+3*b+2) * res;
    float fx = floorf(sx), fy = floorf(sy), fz = floorf(sz);
    unsigned gx = (unsigned)fx, gy = (unsigned)fy, gz = (unsigned)fz;
    float tx = sx-fx, ty = sy-fy, tz = sz-fz;
    unsigned hx0 = gx, hx1 = gx+1u;
    unsigned hy0 = gy*NGP_P1, hy1 = hy0+NGP_P1;
    unsigned hz0 = gz*NGP_P2, hz1 = hz0+NGP_P2;
    const float2* __restrict__ tbl = tables + ((size_t)l << NGP_T);
    float2 v0 = __ldg(tbl + ((hx0^hy0^hz0)&NGP_MASK));
    float2 v1 = __ldg(tbl + ((hx1^hy0^hz0)&NGP_MASK));
    float2 v2 = __ldg(tbl + ((hx0^hy1^hz0)&NGP_MASK));
    float2 v3 = __ldg(tbl + ((hx1^hy1^hz0)&NGP_MASK));
    float2 v4 = __ldg(tbl + ((hx0^hy0^hz1)&NGP_MASK));
    float2 v5 = __ldg(tbl + ((hx1^hy0^hz1)&NGP_MASK));
    float2 v6 = __ldg(tbl + ((hx0^hy1^hz1)&NGP_MASK));
    float2 v7 = __ldg(tbl + ((hx1^hy1^hz1)&NGP_MASK));
    float wx0 = 1.0f-tx, wy0 = 1.0f-ty, wz0 = 1.0f-tz;
    float w00 = wx0*wy0, w10 = tx*wy0, w01 = wx0*ty, w11 = tx*ty;
    float a0 = 0.f, a1 = 0.f, w;
    w = w00*wz0; a0 = fmaf(w,v0.x,a0); a1 = fmaf(w,v0.y,a1);
    w = w10*wz0; a0 = fmaf(w,v1.x,a0); a1 = fmaf(w,v1.y,a1);
    w = w01*wz0; a0 = fmaf(w,v2.x,a0); a1 = fmaf(w,v2.y,a1);
    w = w11*wz0; a0 = fmaf(w,v3.x,a0); a1 = fmaf(w,v3.y,a1);
    w = w00*tz;  a0 = fmaf(w,v4.x,a0); a1 = fmaf(w,v4.y,a1);
    w = w10*tz;  a0 = fmaf(w,v5.x,a0); a1 = fmaf(w,v5.y,a1);
    w = w01*tz;  a0 = fmaf(w,v6.x,a0); a1 = fmaf(w,v6.y,a1);
    w = w11*tz;  a0 = fmaf(w,v7.x,a0); a1 = fmaf(w,v7.y,a1);
    out[(size_t)b*16 + l] = make_float2(a0, a1);
}

extern "C" void kernel_launch(void* const* d_in, const int* in_sizes, int n_in,
                              void* d_out, int out_size)
{
    const float* x = (const float*)d_in[0];
    const float2* tables = (const float2*)d_in[1];
    int npts = in_sizes[0] / 3;

    // Replicate numpy's RES computation bit-for-bit in float64 (same libm,
    // incl. numpy's pow shortcuts). RES is exactly integral at levels
    // 0,3,6,9,12,15, so independent recomputation risks off-by-one in floor.
    ResParams rp;
    double bb = exp((log(512.0) - log(16.0)) / 15.0);
    for (int l = 0; l < NGP_L; l++) {
        double p;
        if (l == 0)      p = 1.0;
        else if (l == 1) p = bb;
        else if (l == 2) p = bb * bb;
        else             p = pow(bb, (double)l);
        rp.r[l] = (float)floor(16.0 * p);
    }

    if (npts > BMAX) {
        int total = npts * 16;
        ngp_flat_kernel<<<(total + 255) / 256, 256>>>(x, tables, (float2*)d_out, rp, npts);
        return;
    }

    void* histAddr = nullptr;
    cudaGetSymbolAddress(&histAddr, g_hist);
    cudaMemsetAsync(histAddr, 0, NB * sizeof(unsigned));

    int blocks = (npts + 255) / 256;
    k_hist<<<blocks, 256>>>(x, npts);
    k_scan<<<1, 1024>>>();
    k_scatter<<<blocks, 256>>>(x, npts);
    k_main<<<(npts + 127) / 128, 128>>>(tables, rp, npts, (float*)d_out);
}

// round 17
// speedup vs baseline: 1.3464x; 1.2900x over previous
#include <cuda_runtime.h>
#include <math.h>
#include <stdint.h>

// NGP multiresolution hash-grid interpolation encoding with Morton bucket sort.
// Round 17: k_main uses ZERO shared memory (smem staging was evicting the
// 228KB L1D carveout that makes sorted gathers fast). Outputs stored directly
// (scattered STG.64). 2 points per thread -> warp covers 64 adjacent points,
// halving per-point gather wavefronts via warp-level line dedup. NB=4096.
// B=262144 points, DIM=3, L=16 levels, T=19, F=2.

#define NGP_L 16
#define NGP_T 19
#define NGP_MASK ((1u << NGP_T) - 1u)
#define NGP_P1 2654435761u
#define NGP_P2 805459861u
#define BMAX 262144
#define NB 4096            // 16^3 Morton buckets

struct ResParams { float r[NGP_L]; };

__device__ unsigned g_hist[NB];
__device__ unsigned g_off[NB];
__device__ float4   g_pk[BMAX];   // sorted (x, y, z, orig_idx_bits)

__device__ __forceinline__ unsigned spread3(unsigned v) {
    return (v & 1u) | ((v & 2u) << 2) | ((v & 4u) << 4) | ((v & 8u) << 6);
}

__device__ __forceinline__ unsigned bucket_of(float x0, float x1, float x2) {
    unsigned bx = (unsigned)(x0 * 16.0f); if (bx > 15u) bx = 15u;
    unsigned by = (unsigned)(x1 * 16.0f); if (by > 15u) by = 15u;
    unsigned bz = (unsigned)(x2 * 16.0f); if (bz > 15u) bz = 15u;
    return spread3(bx) | (spread3(by) << 1) | (spread3(bz) << 2);
}

__global__ void k_hist(const float* __restrict__ x, int n) {
    int b = blockIdx.x * 256 + threadIdx.x;
    if (b >= n) return;
    atomicAdd(&g_hist[bucket_of(x[3*b], x[3*b+1], x[3*b+2])], 1u);
}

// exclusive scan of g_hist (4096 = 1024 threads x 4) -> g_off
__global__ void __launch_bounds__(1024) k_scan() {
    __shared__ unsigned s[1024];
    int t = threadIdx.x;
    unsigned h0 = g_hist[4*t], h1 = g_hist[4*t+1], h2 = g_hist[4*t+2], h3 = g_hist[4*t+3];
    s[t] = h0 + h1 + h2 + h3;
    __syncthreads();
    for (int d = 1; d < 1024; d <<= 1) {
        unsigned v = (t >= d) ? s[t-d] : 0u;
        __syncthreads();
        s[t] += v;
        __syncthreads();
    }
    unsigned excl = (t == 0) ? 0u : s[t-1];
    g_off[4*t]   = excl;
    g_off[4*t+1] = excl + h0;
    g_off[4*t+2] = excl + h0 + h1;
    g_off[4*t+3] = excl + h0 + h1 + h2;
}

__global__ void k_scatter(const float* __restrict__ x, int n) {
    int b = blockIdx.x * 256 + threadIdx.x;
    if (b >= n) return;
    float x0 = x[3*b], x1 = x[3*b+1], x2 = x[3*b+2];
    unsigned p = atomicAdd(&g_off[bucket_of(x0, x1, x2)], 1u);
    g_pk[p] = make_float4(x0, x1, x2, __uint_as_float((unsigned)b));
}

// one level for one point: 8 batched gathers + trilinear accumulate
__device__ __forceinline__ float2 level_point(
    const float2* __restrict__ tbl, float res, float x0, float x1, float x2)
{
    float sx = x0 * res, sy = x1 * res, sz = x2 * res;
    float fx = floorf(sx), fy = floorf(sy), fz = floorf(sz);
    unsigned gx = (unsigned)fx, gy = (unsigned)fy, gz = (unsigned)fz;
    float tx = sx - fx, ty = sy - fy, tz = sz - fz;

    unsigned hx0 = gx,          hx1 = gx + 1u;
    unsigned hy0 = gy * NGP_P1, hy1 = hy0 + NGP_P1;
    unsigned hz0 = gz * NGP_P2, hz1 = hz0 + NGP_P2;

    unsigned i0 = (hx0 ^ hy0 ^ hz0) & NGP_MASK;
    unsigned i1 = (hx1 ^ hy0 ^ hz0) & NGP_MASK;
    unsigned i2 = (hx0 ^ hy1 ^ hz0) & NGP_MASK;
    unsigned i3 = (hx1 ^ hy1 ^ hz0) & NGP_MASK;
    unsigned i4 = (hx0 ^ hy0 ^ hz1) & NGP_MASK;
    unsigned i5 = (hx1 ^ hy0 ^ hz1) & NGP_MASK;
    unsigned i6 = (hx0 ^ hy1 ^ hz1) & NGP_MASK;
    unsigned i7 = (hx1 ^ hy1 ^ hz1) & NGP_MASK;

    float2 v0 = __ldg(tbl + i0);
    float2 v1 = __ldg(tbl + i1);
    float2 v2 = __ldg(tbl + i2);
    float2 v3 = __ldg(tbl + i3);
    float2 v4 = __ldg(tbl + i4);
    float2 v5 = __ldg(tbl + i5);
    float2 v6 = __ldg(tbl + i6);
    float2 v7 = __ldg(tbl + i7);

    float wx0 = 1.0f - tx, wy0 = 1.0f - ty, wz0 = 1.0f - tz;
    float w00 = wx0 * wy0, w10 = tx * wy0, w01 = wx0 * ty, w11 = tx * ty;

    float a0 = 0.0f, a1 = 0.0f, wt;
    wt = w00 * wz0; a0 = fmaf(wt, v0.x, a0); a1 = fmaf(wt, v0.y, a1);
    wt = w10 * wz0; a0 = fmaf(wt, v1.x, a0); a1 = fmaf(wt, v1.y, a1);
    wt = w01 * wz0; a0 = fmaf(wt, v2.x, a0); a1 = fmaf(wt, v2.y, a1);
    wt = w11 * wz0; a0 = fmaf(wt, v3.x, a0); a1 = fmaf(wt, v3.y, a1);
    wt = w00 * tz;  a0 = fmaf(wt, v4.x, a0); a1 = fmaf(wt, v4.y, a1);
    wt = w10 * tz;  a0 = fmaf(wt, v5.x, a0); a1 = fmaf(wt, v5.y, a1);
    wt = w01 * tz;  a0 = fmaf(wt, v6.x, a0); a1 = fmaf(wt, v6.y, a1);
    wt = w11 * tz;  a0 = fmaf(wt, v7.x, a0); a1 = fmaf(wt, v7.y, a1);
    return make_float2(a0, a1);
}

// Main: thread = 2 consecutive sorted points, loops 16 levels, no smem
// (preserves full 228KB L1D for table caching). Direct scattered STG.64
// stores to out[orig*16 + l].
__global__ void __launch_bounds__(256) k_main(
    const float2* __restrict__ tables, ResParams rp, int n,
    float2* __restrict__ out2)
{
    int base = (blockIdx.x * 256 + threadIdx.x) * 2;
    if (base >= n) return;
    bool has2 = (base + 1) < n;

    float4 pA = g_pk[base];
    float4 pB = g_pk[has2 ? base + 1 : base];
    unsigned oA = __float_as_uint(pA.w);
    unsigned oB = __float_as_uint(pB.w);

    #pragma unroll 1
    for (int l = 0; l < NGP_L; l++) {
        float res = rp.r[l];
        const float2* __restrict__ tbl = tables + ((size_t)l << NGP_T);
        float2 rA = level_point(tbl, res, pA.x, pA.y, pA.z);
        float2 rB = level_point(tbl, res, pB.x, pB.y, pB.z);
        out2[(size_t)oA * 16 + l] = rA;
        if (has2) out2[(size_t)oB * 16 + l] = rB;
    }
}

// Fallback (round-1 style flat kernel) if npts exceeds scratch capacity.
__global__ void __launch_bounds__(256, 8) ngp_flat_kernel(
    const float* __restrict__ x, const float2* __restrict__ tables,
    float2* __restrict__ out, ResParams rp, int npts)
{
    int t = blockIdx.x * 256 + threadIdx.x;
    int b = t >> 4, l = t & 15;
    if (b >= npts) return;
    const float2* __restrict__ tbl = tables + ((size_t)l << NGP_T);
    float2 r = level_point(tbl, rp.r[l], __ldg(x+3*b), __ldg(x+3*b+1), __ldg(x+3*b+2));
    out[(size_t)b*16 + l] = r;
}

extern "C" void kernel_launch(void* const* d_in, const int* in_sizes, int n_in,
                              void* d_out, int out_size)
{
    const float* x = (const float*)d_in[0];
    const float2* tables = (const float2*)d_in[1];
    int npts = in_sizes[0] / 3;

    // Replicate numpy's RES computation bit-for-bit in float64 (same libm,
    // incl. numpy's pow shortcuts). RES is exactly integral at levels
    // 0,3,6,9,12,15, so independent recomputation risks off-by-one in floor.
    ResParams rp;
    double bb = exp((log(512.0) - log(16.0)) / 15.0);
    for (int l = 0; l < NGP_L; l++) {
        double p;
        if (l == 0)      p = 1.0;
        else if (l == 1) p = bb;
        else if (l == 2) p = bb * bb;
        else             p = pow(bb, (double)l);
        rp.r[l] = (float)floor(16.0 * p);
    }

    if (npts > BMAX) {
        int total = npts * 16;
        ngp_flat_kernel<<<(total + 255) / 256, 256>>>(x, tables, (float2*)d_out, rp, npts);
        return;
    }

    void* histAddr = nullptr;
    cudaGetSymbolAddress(&histAddr, g_hist);
    cudaMemsetAsync(histAddr, 0, NB * sizeof(unsigned));

    int blocks = (npts + 255) / 256;
    k_hist<<<blocks, 256>>>(x, npts);
    k_scan<<<1, 1024>>>();
    k_scatter<<<blocks, 256>>>(x, npts);
    int pthreads = (npts + 1) / 2;
    k_main<<<(pthreads + 255) / 256, 256>>>(tables, rp, npts, (float2*)d_out);
}